// round 4
// baseline (speedup 1.0000x reference)
#include <cuda_runtime.h>
#include <cuda_bf16.h>
#include <cstdint>

#define NN 100000
#define EE 1600000
#define FF 128
#define RR 50
#define BN_EPS 1e-3f

// Scratch (allocation-free rule: device globals)
__device__ float g_h[(size_t)NN * FF];    // batchnormed features
__device__ float g_pre[(size_t)NN * FF];  // coeff-residual + aggregated messages
__device__ int   g_deg[NN];               // per-row edge count
__device__ int   g_rowptr[NN + 1];        // CSR row pointers
__device__ int   g_cursor[NN];            // fill cursors
__device__ int2  g_cpack[EE];             // packed (col, w_bits) per CSR slot

// ---------------------------------------------------------------------------
// Kernel 1: BatchNorm (inference) into g_h; also zero g_deg.
// BN params folded to scale/shift in SMEM once per block.
// ---------------------------------------------------------------------------
__global__ void __launch_bounds__(256)
bn_kernel(const float* __restrict__ x,
          const float* __restrict__ gamma,
          const float* __restrict__ beta,
          const float* __restrict__ mean,
          const float* __restrict__ var)
{
    __shared__ float s_scale[FF], s_shift[FF];
    int tid = threadIdx.x;
    if (tid < FF) {
        float sc = gamma[tid] * rsqrtf(var[tid] + BN_EPS);
        s_scale[tid] = sc;
        s_shift[tid] = beta[tid] - mean[tid] * sc;
    }
    __syncthreads();

    int idx = blockIdx.x * blockDim.x + tid;
    if (idx < NN) g_deg[idx] = 0;                 // covered: 12500*256 >= NN
    if (idx >= NN * (FF / 4)) return;

    int c = (idx & 31) * 4;
    float4 xv = ((const float4*)x)[idx];
    float4 hv;
    hv.x = xv.x * s_scale[c + 0] + s_shift[c + 0];
    hv.y = xv.y * s_scale[c + 1] + s_shift[c + 1];
    hv.z = xv.z * s_scale[c + 2] + s_shift[c + 2];
    hv.w = xv.w * s_scale[c + 3] + s_shift[c + 3];
    ((float4*)g_h)[idx] = hv;
}

// ---------------------------------------------------------------------------
// Kernel 2: degree histogram
// ---------------------------------------------------------------------------
__global__ void hist_kernel(const int* __restrict__ rows)
{
    int e = blockIdx.x * blockDim.x + threadIdx.x;
    if (e < EE) atomicAdd(&g_deg[rows[e]], 1);
}

// ---------------------------------------------------------------------------
// Kernel 3: exclusive scan of g_deg -> g_rowptr / g_cursor. Single block.
// Per-thread chunk of 100 (int4 reads), block scan of partials.
// ---------------------------------------------------------------------------
#define SCAN_T 1024
#define SCAN_CH 100

__global__ void __launch_bounds__(SCAN_T)
scan_kernel()
{
    __shared__ int part[SCAN_T];
    int t = threadIdx.x;
    int base = t * SCAN_CH;

    int s = 0;
#pragma unroll
    for (int i = 0; i < SCAN_CH; i++) {
        int idx = base + i;
        if (idx < NN) s += g_deg[idx];
    }
    part[t] = s;
    __syncthreads();

    // Hillis-Steele inclusive scan
#pragma unroll
    for (int off = 1; off < SCAN_T; off <<= 1) {
        int v = (t >= off) ? part[t - off] : 0;
        __syncthreads();
        part[t] += v;
        __syncthreads();
    }

    int run = (t == 0) ? 0 : part[t - 1];
#pragma unroll
    for (int i = 0; i < SCAN_CH; i++) {
        int idx = base + i;
        if (idx < NN) {
            g_rowptr[idx] = run;
            g_cursor[idx] = run;
            run += g_deg[idx];
        }
    }
    if (t == SCAN_T - 1) g_rowptr[NN] = part[SCAN_T - 1];
}

// ---------------------------------------------------------------------------
// Kernel 4: fill CSR slots with (col, precomputed weight)
// ---------------------------------------------------------------------------
__global__ void fill_kernel(const int*   __restrict__ rows,
                            const int*   __restrict__ cols,
                            const float* __restrict__ vals,
                            const int*   __restrict__ rels,
                            const float* __restrict__ rc)
{
    int e = blockIdx.x * blockDim.x + threadIdx.x;
    if (e >= EE) return;
    int r = rows[e];
    float w = vals[e] / (rc[rels[e]] + 1.0f);
    int pos = atomicAdd(&g_cursor[r], 1);
    int2 p;
    p.x = cols[e];
    p.y = __float_as_int(w);
    g_cpack[pos] = p;
}

// ---------------------------------------------------------------------------
// Kernel 5: SpMM-CSR, one warp per node, register accumulation, coeff fused.
// pre[i] = h[i]*(coeff[i]+1) + sum_e w_e * h[col_e]; single write, no atomics.
// ---------------------------------------------------------------------------
__global__ void __launch_bounds__(256)
spmm_csr_kernel(const float* __restrict__ coeff)
{
    int lane = threadIdx.x & 31;
    int node = blockIdx.x * (blockDim.x >> 5) + (threadIdx.x >> 5);
    if (node >= NN) return;

    const float4* hrow = (const float4*)(g_h + (size_t)node * FF);
    float4 hv = hrow[lane];
    float cm = coeff[node] + 1.0f;
    float ax = hv.x * cm, ay = hv.y * cm, az = hv.z * cm, aw = hv.w * cm;

    int p   = g_rowptr[node];
    int end = g_rowptr[node + 1];

    for (; p + 4 <= end; p += 4) {
        int2 e0 = g_cpack[p + 0];
        int2 e1 = g_cpack[p + 1];
        int2 e2 = g_cpack[p + 2];
        int2 e3 = g_cpack[p + 3];
        float4 h0 = __ldg(((const float4*)(g_h + (size_t)e0.x * FF)) + lane);
        float4 h1 = __ldg(((const float4*)(g_h + (size_t)e1.x * FF)) + lane);
        float4 h2 = __ldg(((const float4*)(g_h + (size_t)e2.x * FF)) + lane);
        float4 h3 = __ldg(((const float4*)(g_h + (size_t)e3.x * FF)) + lane);
        float w0 = __int_as_float(e0.y), w1 = __int_as_float(e1.y);
        float w2 = __int_as_float(e2.y), w3 = __int_as_float(e3.y);
        ax += w0 * h0.x + w1 * h1.x + w2 * h2.x + w3 * h3.x;
        ay += w0 * h0.y + w1 * h1.y + w2 * h2.y + w3 * h3.y;
        az += w0 * h0.z + w1 * h1.z + w2 * h2.z + w3 * h3.z;
        aw += w0 * h0.w + w1 * h1.w + w2 * h2.w + w3 * h3.w;
    }
    for (; p < end; p++) {
        int2 e0 = g_cpack[p];
        float4 h0 = __ldg(((const float4*)(g_h + (size_t)e0.x * FF)) + lane);
        float w0 = __int_as_float(e0.y);
        ax += w0 * h0.x; ay += w0 * h0.y; az += w0 * h0.z; aw += w0 * h0.w;
    }

    float4 outv = make_float4(ax, ay, az, aw);
    ((float4*)(g_pre + (size_t)node * FF))[lane] = outv;
}

// ---------------------------------------------------------------------------
// Kernel 6: out = pre @ W + bias, packed-f32x2 FFMA.
// Block: 256 threads, tile 128x128, thread tile 8x8.
// ---------------------------------------------------------------------------
#define AS_STRIDE 132

__global__ void __launch_bounds__(256)
gemm_kernel(const float* __restrict__ W,
            const float* __restrict__ bias,
            float* __restrict__ out)
{
    extern __shared__ float sm[];
    float* Ws = sm;                 // [128][128]
    float* As = sm + FF * FF;       // [128][AS_STRIDE]

    int tid  = threadIdx.x;
    int row0 = blockIdx.x * 128;

    for (int i = tid; i < FF * FF / 4; i += 256)
        ((float4*)Ws)[i] = ((const float4*)W)[i];

    for (int i = tid; i < 128 * (FF / 4); i += 256) {
        int lr = i >> 5;
        int c4 = i & 31;
        int gr = row0 + lr;
        float4 v = make_float4(0.f, 0.f, 0.f, 0.f);
        if (gr < NN) v = ((const float4*)g_pre)[(size_t)gr * 32 + c4];
        ((float4*)(As + lr * AS_STRIDE))[c4] = v;
    }
    __syncthreads();

    int rg = tid >> 4;
    int cg = tid & 15;
    int rbase = rg * 8;
    int cbase = cg * 8;

    unsigned long long acc[8][4];
#pragma unroll
    for (int i = 0; i < 8; i++)
#pragma unroll
        for (int j = 0; j < 4; j++)
            acc[i][j] = 0ull;

#pragma unroll 4
    for (int k = 0; k < FF; k++) {
        const float* wrow = Ws + k * FF + cbase;
        ulonglong2 b01 = *(const ulonglong2*)(wrow);
        ulonglong2 b23 = *(const ulonglong2*)(wrow + 4);
        unsigned long long bb0 = b01.x, bb1 = b01.y, bb2 = b23.x, bb3 = b23.y;

#pragma unroll
        for (int i = 0; i < 8; i++) {
            float a = As[(rbase + i) * AS_STRIDE + k];
            unsigned long long ap;
            asm("mov.b64 %0, {%1, %1};" : "=l"(ap) : "r"(__float_as_uint(a)));
            asm("fma.rn.f32x2 %0, %1, %2, %0;" : "+l"(acc[i][0]) : "l"(ap), "l"(bb0));
            asm("fma.rn.f32x2 %0, %1, %2, %0;" : "+l"(acc[i][1]) : "l"(ap), "l"(bb1));
            asm("fma.rn.f32x2 %0, %1, %2, %0;" : "+l"(acc[i][2]) : "l"(ap), "l"(bb2));
            asm("fma.rn.f32x2 %0, %1, %2, %0;" : "+l"(acc[i][3]) : "l"(ap), "l"(bb3));
        }
    }

    float bv[8];
#pragma unroll
    for (int j = 0; j < 8; j++) bv[j] = bias[cbase + j];

#pragma unroll
    for (int i = 0; i < 8; i++) {
        int row = row0 + rbase + i;
        if (row >= NN) break;
        float* orow = out + (size_t)row * FF + cbase;
#pragma unroll
        for (int j = 0; j < 4; j++) {
            unsigned int lo, hi;
            asm("mov.b64 {%0, %1}, %2;" : "=r"(lo), "=r"(hi) : "l"(acc[i][j]));
            float2 v;
            v.x = __uint_as_float(lo) + bv[2 * j + 0];
            v.y = __uint_as_float(hi) + bv[2 * j + 1];
            *(float2*)(orow + 2 * j) = v;
        }
    }
}

// ---------------------------------------------------------------------------
extern "C" void kernel_launch(void* const* d_in, const int* in_sizes, int n_in,
                              void* d_out, int out_size)
{
    const float* x          = (const float*)d_in[0];
    const int*   edge_rows  = (const int*)  d_in[1];
    const int*   edge_cols  = (const int*)  d_in[2];
    const float* edge_vals  = (const float*)d_in[3];
    const int*   rel_ids    = (const int*)  d_in[4];
    const float* rel_coeffs = (const float*)d_in[5];
    const float* coeff_k    = (const float*)d_in[6];
    const float* dense_W    = (const float*)d_in[7];
    const float* dense_b    = (const float*)d_in[8];
    const float* bn_gamma   = (const float*)d_in[9];
    const float* bn_beta    = (const float*)d_in[10];
    const float* bn_mean    = (const float*)d_in[11];
    const float* bn_var     = (const float*)d_in[12];
    float*       out        = (float*)d_out;

    // 1) BN -> g_h, zero deg
    {
        int total = NN * (FF / 4);
        int blocks = (total + 255) / 256;
        bn_kernel<<<blocks, 256>>>(x, bn_gamma, bn_beta, bn_mean, bn_var);
    }
    // 2) degree histogram
    hist_kernel<<<(EE + 255) / 256, 256>>>(edge_rows);
    // 3) prefix scan
    scan_kernel<<<1, SCAN_T>>>();
    // 4) CSR fill (weights precomputed)
    fill_kernel<<<(EE + 255) / 256, 256>>>(edge_rows, edge_cols, edge_vals,
                                           rel_ids, rel_coeffs);
    // 5) SpMM-CSR + coeff residual
    {
        int blocks = (NN + 7) / 8;   // 8 warps per block
        spmm_csr_kernel<<<blocks, 256>>>(coeff_k);
    }
    // 6) Dense GEMM
    {
        int smem = (FF * FF + 128 * AS_STRIDE) * sizeof(float);
        cudaFuncSetAttribute(gemm_kernel,
                             cudaFuncAttributeMaxDynamicSharedMemorySize, smem);
        int blocks = (NN + 127) / 128;
        gemm_kernel<<<blocks, 256, smem>>>(dense_W, dense_b, out);
    }
}

// round 5
// speedup vs baseline: 2.3379x; 2.3379x over previous
#include <cuda_runtime.h>
#include <cuda_bf16.h>
#include <cstdint>

#define NN 100000
#define EE 1600000
#define FF 128
#define RR 50
#define BN_EPS 1e-3f

// Scratch (allocation-free rule: device globals)
__device__ float g_h[(size_t)NN * FF];    // batchnormed features
__device__ float g_pre[(size_t)NN * FF];  // coeff-residual + aggregated messages
__device__ int   g_deg[NN];               // per-row edge count
__device__ int   g_rowptr[NN + 1];        // CSR row pointers
__device__ int   g_cursor[NN];            // fill cursors
__device__ int2  g_cpack[EE];             // packed (col, w_bits) per CSR slot
__device__ int   g_blocksum[64];          // scan partials
__device__ int   g_blockoff[64];          // scanned partials

// ---------------------------------------------------------------------------
// Kernel 1: BatchNorm (inference) into g_h; also zero g_deg.
// ---------------------------------------------------------------------------
__global__ void __launch_bounds__(256)
bn_kernel(const float* __restrict__ x,
          const float* __restrict__ gamma,
          const float* __restrict__ beta,
          const float* __restrict__ mean,
          const float* __restrict__ var)
{
    __shared__ float s_scale[FF], s_shift[FF];
    int tid = threadIdx.x;
    if (tid < FF) {
        float sc = gamma[tid] * rsqrtf(var[tid] + BN_EPS);
        s_scale[tid] = sc;
        s_shift[tid] = beta[tid] - mean[tid] * sc;
    }
    __syncthreads();

    int idx = blockIdx.x * blockDim.x + tid;
    if (idx < NN) g_deg[idx] = 0;                 // 12500*256 >= NN
    if (idx >= NN * (FF / 4)) return;

    int c = (idx & 31) * 4;
    float4 xv = ((const float4*)x)[idx];
    float4 hv;
    hv.x = xv.x * s_scale[c + 0] + s_shift[c + 0];
    hv.y = xv.y * s_scale[c + 1] + s_shift[c + 1];
    hv.z = xv.z * s_scale[c + 2] + s_shift[c + 2];
    hv.w = xv.w * s_scale[c + 3] + s_shift[c + 3];
    ((float4*)g_h)[idx] = hv;
}

// ---------------------------------------------------------------------------
// Kernel 2: degree histogram
// ---------------------------------------------------------------------------
__global__ void hist_kernel(const int* __restrict__ rows)
{
    int e = blockIdx.x * blockDim.x + threadIdx.x;
    if (e < EE) atomicAdd(&g_deg[rows[e]], 1);
}

// ---------------------------------------------------------------------------
// Kernel 3a: block-local exclusive scan. 25 blocks x 256 thr x 16 elems.
// All gmem access coalesced via SMEM staging.
// ---------------------------------------------------------------------------
#define SCB 4096
#define SCAN_BLOCKS ((NN + SCB - 1) / SCB)   // 25

__global__ void __launch_bounds__(256)
scan_blocks_kernel()
{
    __shared__ int sh[SCB];
    __shared__ int warpsums[8];
    int b = blockIdx.x, t = threadIdx.x;
    int base = b * SCB;

    // coalesced load
#pragma unroll
    for (int i = 0; i < 16; i++) {
        int idx = base + i * 256 + t;
        sh[i * 256 + t] = (idx < NN) ? g_deg[idx] : 0;
    }
    __syncthreads();

    // per-thread sum of its contiguous 16
    int o = t * 16;
    int my = 0;
#pragma unroll
    for (int i = 0; i < 16; i++) my += sh[o + i];

    // warp inclusive scan of per-thread sums
    int lane = t & 31, wid = t >> 5;
    int pref = my;
#pragma unroll
    for (int d = 1; d < 32; d <<= 1) {
        int v = __shfl_up_sync(0xffffffffu, pref, d);
        if (lane >= d) pref += v;
    }
    if (lane == 31) warpsums[wid] = pref;
    __syncthreads();

    int woff = 0;
#pragma unroll
    for (int i = 0; i < 8; i++)
        if (i < wid) woff += warpsums[i];

    // write block-local exclusive scan back into SMEM
    int run = woff + pref - my;
#pragma unroll
    for (int i = 0; i < 16; i++) {
        int v = sh[o + i];
        sh[o + i] = run;
        run += v;
    }
    if (t == 255) g_blocksum[b] = run;   // block total
    __syncthreads();

    // coalesced store of block-local exclusive scan
#pragma unroll
    for (int i = 0; i < 16; i++) {
        int idx = base + i * 256 + t;
        if (idx < NN) g_rowptr[idx] = sh[i * 256 + t];
    }
}

// ---------------------------------------------------------------------------
// Kernel 3b: scan the 25 block sums with one warp.
// ---------------------------------------------------------------------------
__global__ void scan_tops_kernel()
{
    int t = threadIdx.x;
    int v = (t < SCAN_BLOCKS) ? g_blocksum[t] : 0;
    int p = v;
#pragma unroll
    for (int d = 1; d < 32; d <<= 1) {
        int u = __shfl_up_sync(0xffffffffu, p, d);
        if (t >= d) p += u;
    }
    if (t < SCAN_BLOCKS) g_blockoff[t] = p - v;
    if (t == 31) g_rowptr[NN] = p;       // grand total == EE
}

// ---------------------------------------------------------------------------
// Kernel 3c: add block offsets; init cursors.
// ---------------------------------------------------------------------------
__global__ void scan_addoff_kernel()
{
    int i = blockIdx.x * blockDim.x + threadIdx.x;
    if (i < NN) {
        int v = g_rowptr[i] + g_blockoff[i >> 12];   // SCB == 4096 == 2^12
        g_rowptr[i] = v;
        g_cursor[i] = v;
    }
}

// ---------------------------------------------------------------------------
// Kernel 4: fill CSR slots with (col, precomputed weight)
// ---------------------------------------------------------------------------
__global__ void fill_kernel(const int*   __restrict__ rows,
                            const int*   __restrict__ cols,
                            const float* __restrict__ vals,
                            const int*   __restrict__ rels,
                            const float* __restrict__ rc)
{
    int e = blockIdx.x * blockDim.x + threadIdx.x;
    if (e >= EE) return;
    int r = rows[e];
    float w = vals[e] / (rc[rels[e]] + 1.0f);
    int pos = atomicAdd(&g_cursor[r], 1);
    int2 p;
    p.x = cols[e];
    p.y = __float_as_int(w);
    g_cpack[pos] = p;
}

// ---------------------------------------------------------------------------
// Kernel 5: SpMM-CSR, one warp per node, register accumulation, coeff fused.
// 8-wide unroll for MLP to cover L2 latency.
// ---------------------------------------------------------------------------
__global__ void __launch_bounds__(256)
spmm_csr_kernel(const float* __restrict__ coeff)
{
    int lane = threadIdx.x & 31;
    int node = blockIdx.x * (blockDim.x >> 5) + (threadIdx.x >> 5);
    if (node >= NN) return;

    const float4* hrow = (const float4*)(g_h + (size_t)node * FF);
    float4 hv = hrow[lane];
    float cm = coeff[node] + 1.0f;
    float ax = hv.x * cm, ay = hv.y * cm, az = hv.z * cm, aw = hv.w * cm;

    int p   = g_rowptr[node];
    int end = g_rowptr[node + 1];

    for (; p + 8 <= end; p += 8) {
        int2 e0 = g_cpack[p + 0], e1 = g_cpack[p + 1];
        int2 e2 = g_cpack[p + 2], e3 = g_cpack[p + 3];
        int2 e4 = g_cpack[p + 4], e5 = g_cpack[p + 5];
        int2 e6 = g_cpack[p + 6], e7 = g_cpack[p + 7];
        float4 h0 = __ldg(((const float4*)(g_h + (size_t)e0.x * FF)) + lane);
        float4 h1 = __ldg(((const float4*)(g_h + (size_t)e1.x * FF)) + lane);
        float4 h2 = __ldg(((const float4*)(g_h + (size_t)e2.x * FF)) + lane);
        float4 h3 = __ldg(((const float4*)(g_h + (size_t)e3.x * FF)) + lane);
        float4 h4 = __ldg(((const float4*)(g_h + (size_t)e4.x * FF)) + lane);
        float4 h5 = __ldg(((const float4*)(g_h + (size_t)e5.x * FF)) + lane);
        float4 h6 = __ldg(((const float4*)(g_h + (size_t)e6.x * FF)) + lane);
        float4 h7 = __ldg(((const float4*)(g_h + (size_t)e7.x * FF)) + lane);
        float w0 = __int_as_float(e0.y), w1 = __int_as_float(e1.y);
        float w2 = __int_as_float(e2.y), w3 = __int_as_float(e3.y);
        float w4 = __int_as_float(e4.y), w5 = __int_as_float(e5.y);
        float w6 = __int_as_float(e6.y), w7 = __int_as_float(e7.y);
        ax += w0*h0.x + w1*h1.x + w2*h2.x + w3*h3.x + w4*h4.x + w5*h5.x + w6*h6.x + w7*h7.x;
        ay += w0*h0.y + w1*h1.y + w2*h2.y + w3*h3.y + w4*h4.y + w5*h5.y + w6*h6.y + w7*h7.y;
        az += w0*h0.z + w1*h1.z + w2*h2.z + w3*h3.z + w4*h4.z + w5*h5.z + w6*h6.z + w7*h7.z;
        aw += w0*h0.w + w1*h1.w + w2*h2.w + w3*h3.w + w4*h4.w + w5*h5.w + w6*h6.w + w7*h7.w;
    }
    for (; p < end; p++) {
        int2 e0 = g_cpack[p];
        float4 h0 = __ldg(((const float4*)(g_h + (size_t)e0.x * FF)) + lane);
        float w0 = __int_as_float(e0.y);
        ax += w0 * h0.x; ay += w0 * h0.y; az += w0 * h0.z; aw += w0 * h0.w;
    }

    ((float4*)(g_pre + (size_t)node * FF))[lane] = make_float4(ax, ay, az, aw);
}

// ---------------------------------------------------------------------------
// Kernel 6: out = pre @ W + bias, packed-f32x2 FFMA.
// ---------------------------------------------------------------------------
#define AS_STRIDE 132

__global__ void __launch_bounds__(256)
gemm_kernel(const float* __restrict__ W,
            const float* __restrict__ bias,
            float* __restrict__ out)
{
    extern __shared__ float sm[];
    float* Ws = sm;                 // [128][128]
    float* As = sm + FF * FF;       // [128][AS_STRIDE]

    int tid  = threadIdx.x;
    int row0 = blockIdx.x * 128;

    for (int i = tid; i < FF * FF / 4; i += 256)
        ((float4*)Ws)[i] = ((const float4*)W)[i];

    for (int i = tid; i < 128 * (FF / 4); i += 256) {
        int lr = i >> 5;
        int c4 = i & 31;
        int gr = row0 + lr;
        float4 v = make_float4(0.f, 0.f, 0.f, 0.f);
        if (gr < NN) v = ((const float4*)g_pre)[(size_t)gr * 32 + c4];
        ((float4*)(As + lr * AS_STRIDE))[c4] = v;
    }
    __syncthreads();

    int rg = tid >> 4;
    int cg = tid & 15;
    int rbase = rg * 8;
    int cbase = cg * 8;

    unsigned long long acc[8][4];
#pragma unroll
    for (int i = 0; i < 8; i++)
#pragma unroll
        for (int j = 0; j < 4; j++)
            acc[i][j] = 0ull;

#pragma unroll 4
    for (int k = 0; k < FF; k++) {
        const float* wrow = Ws + k * FF + cbase;
        ulonglong2 b01 = *(const ulonglong2*)(wrow);
        ulonglong2 b23 = *(const ulonglong2*)(wrow + 4);
        unsigned long long bb0 = b01.x, bb1 = b01.y, bb2 = b23.x, bb3 = b23.y;

#pragma unroll
        for (int i = 0; i < 8; i++) {
            float a = As[(rbase + i) * AS_STRIDE + k];
            unsigned long long ap;
            asm("mov.b64 %0, {%1, %1};" : "=l"(ap) : "r"(__float_as_uint(a)));
            asm("fma.rn.f32x2 %0, %1, %2, %0;" : "+l"(acc[i][0]) : "l"(ap), "l"(bb0));
            asm("fma.rn.f32x2 %0, %1, %2, %0;" : "+l"(acc[i][1]) : "l"(ap), "l"(bb1));
            asm("fma.rn.f32x2 %0, %1, %2, %0;" : "+l"(acc[i][2]) : "l"(ap), "l"(bb2));
            asm("fma.rn.f32x2 %0, %1, %2, %0;" : "+l"(acc[i][3]) : "l"(ap), "l"(bb3));
        }
    }

    float bv[8];
#pragma unroll
    for (int j = 0; j < 8; j++) bv[j] = bias[cbase + j];

#pragma unroll
    for (int i = 0; i < 8; i++) {
        int row = row0 + rbase + i;
        if (row >= NN) break;
        float* orow = out + (size_t)row * FF + cbase;
#pragma unroll
        for (int j = 0; j < 4; j++) {
            unsigned int lo, hi;
            asm("mov.b64 {%0, %1}, %2;" : "=r"(lo), "=r"(hi) : "l"(acc[i][j]));
            float2 v;
            v.x = __uint_as_float(lo) + bv[2 * j + 0];
            v.y = __uint_as_float(hi) + bv[2 * j + 1];
            *(float2*)(orow + 2 * j) = v;
        }
    }
}

// ---------------------------------------------------------------------------
extern "C" void kernel_launch(void* const* d_in, const int* in_sizes, int n_in,
                              void* d_out, int out_size)
{
    const float* x          = (const float*)d_in[0];
    const int*   edge_rows  = (const int*)  d_in[1];
    const int*   edge_cols  = (const int*)  d_in[2];
    const float* edge_vals  = (const float*)d_in[3];
    const int*   rel_ids    = (const int*)  d_in[4];
    const float* rel_coeffs = (const float*)d_in[5];
    const float* coeff_k    = (const float*)d_in[6];
    const float* dense_W    = (const float*)d_in[7];
    const float* dense_b    = (const float*)d_in[8];
    const float* bn_gamma   = (const float*)d_in[9];
    const float* bn_beta    = (const float*)d_in[10];
    const float* bn_mean    = (const float*)d_in[11];
    const float* bn_var     = (const float*)d_in[12];
    float*       out        = (float*)d_out;

    // 1) BN -> g_h, zero deg
    {
        int total = NN * (FF / 4);
        bn_kernel<<<(total + 255) / 256, 256>>>(x, bn_gamma, bn_beta, bn_mean, bn_var);
    }
    // 2) degree histogram
    hist_kernel<<<(EE + 255) / 256, 256>>>(edge_rows);
    // 3) multi-block exclusive scan
    scan_blocks_kernel<<<SCAN_BLOCKS, 256>>>();
    scan_tops_kernel<<<1, 32>>>();
    scan_addoff_kernel<<<(NN + 255) / 256, 256>>>();
    // 4) CSR fill (weights precomputed)
    fill_kernel<<<(EE + 255) / 256, 256>>>(edge_rows, edge_cols, edge_vals,
                                           rel_ids, rel_coeffs);
    // 5) SpMM-CSR + coeff residual
    spmm_csr_kernel<<<(NN + 7) / 8, 256>>>(coeff_k);
    // 6) Dense GEMM
    {
        int smem = (FF * FF + 128 * AS_STRIDE) * sizeof(float);
        cudaFuncSetAttribute(gemm_kernel,
                             cudaFuncAttributeMaxDynamicSharedMemorySize, smem);
        gemm_kernel<<<(NN + 127) / 128, 256, smem>>>(dense_W, dense_b, out);
    }
}